// round 16
// baseline (speedup 1.0000x reference)
#include <cuda_runtime.h>
#include <cuda_fp16.h>
#include <mma.h>

#define NN  100000
#define EE  1600000
#define INF 128
#define HH  64
typedef unsigned long long u64;
using namespace nvcuda;

#define PACKAB(d,a,b) asm("mov.b64 %0,{%1,%2};" : "=l"(d) : "r"(__float_as_uint(a)), "r"(__float_as_uint(b)))
#define UNPACK2(a,b,d) do { unsigned _ua,_ub; \
    asm("mov.b64 {%0,%1},%2;" : "=r"(_ua),"=r"(_ub) : "l"(d)); \
    a=__uint_as_float(_ua); b=__uint_as_float(_ub); } while(0)

__device__ __forceinline__ unsigned h2_to_u(__half2 h) {
    union { __half2 h; unsigned u; } c; c.h = h; return c.u;
}
__device__ __forceinline__ float2 u_to_f2(unsigned u) {
    union { unsigned u; __half2 h; } c; c.u = u; return __half22float2(c.h);
}

// ---------------- device scratch ----------------
__device__ float  g_ori[NN * HH];   // lin output fp32 (residual source)
__device__ __half g_t0 [NN * HH];   // current t (dinv-prescaled, fp16)
__device__ __half g_t1 [NN * HH];   // next t
__device__ float  g_dinv[NN];
__device__ int    g_cnt[NN];        // zero at load; k_fill drains it back to 0
__device__ int    g_ptr[NN + 1];
__device__ int    g_blk[128];
__device__ int    g_csr[EE];

// ---------------- CSR construction ----------------
__global__ void k_count(const int4* __restrict__ dst4, int e4) {
    int i = blockIdx.x * blockDim.x + threadIdx.x;
    if (i < e4) {
        int4 d = dst4[i];
        atomicAdd(&g_cnt[d.x], 1);
        atomicAdd(&g_cnt[d.y], 1);
        atomicAdd(&g_cnt[d.z], 1);
        atomicAdd(&g_cnt[d.w], 1);
    }
}

__global__ void k_scanA(int n) {
    __shared__ int s[1024];
    int tid = threadIdx.x;
    int i = blockIdx.x * 1024 + tid;
    int c = (i < n) ? g_cnt[i] : 0;
    s[tid] = c;
    __syncthreads();
    #pragma unroll
    for (int off = 1; off < 1024; off <<= 1) {
        int t = (tid >= off) ? s[tid - off] : 0;
        __syncthreads();
        s[tid] += t;
        __syncthreads();
    }
    if (i < n) {
        g_ptr[i] = s[tid] - c;
        g_dinv[i] = rsqrtf((float)(c + 1));
    }
    if (tid == 1023) g_blk[blockIdx.x] = s[1023];
}

__global__ void k_scanC(int nb, int n) {
    __shared__ int pref[128];
    int t = threadIdx.x;
    if (t < 128) pref[t] = (t < nb) ? g_blk[t] : 0;
    __syncthreads();
    #pragma unroll
    for (int off = 1; off < 128; off <<= 1) {
        int v = 0;
        if (t < 128 && t >= off) v = pref[t - off];
        __syncthreads();
        if (t < 128) pref[t] += v;
        __syncthreads();
    }
    int b = blockIdx.x;
    int base = (b == 0) ? 0 : pref[b - 1];
    int i = b * 1024 + t;
    if (i < n) g_ptr[i] += base;
    if (b == 0 && t == 0) g_ptr[n] = pref[127];
}

__global__ void k_fill(const int4* __restrict__ src4, const int4* __restrict__ dst4, int e4) {
    int i = blockIdx.x * blockDim.x + threadIdx.x;
    if (i < e4) {
        int4 s = src4[i];
        int4 d = dst4[i];
        g_csr[g_ptr[d.x] + atomicSub(&g_cnt[d.x], 1) - 1] = s.x;
        g_csr[g_ptr[d.y] + atomicSub(&g_cnt[d.y], 1) - 1] = s.y;
        g_csr[g_ptr[d.z] + atomicSub(&g_cnt[d.z], 1) - 1] = s.z;
        g_csr[g_ptr[d.w] + atomicSub(&g_cnt[d.w], 1) - 1] = s.w;
    }
}

// ------------- lin GEMM via wmma: ori = in[n,128] @ W[128,64] + b ; t0 = fp16(dinv*ori) -------------
#define LN_SMEM (18432 + 34816 + 256)
__global__ void __launch_bounds__(256) k_lin(const float* __restrict__ A,
                                             const float* __restrict__ W,
                                             const float* __restrict__ bias,
                                             float* __restrict__ out,
                                             __half* __restrict__ outh, int n) {
    extern __shared__ char sm[];
    __half* sW = (__half*)sm;                       // [128][72]
    __half* sA = (__half*)(sm + 18432);             // [128][136]
    float*  sB = (float*)(sm + 53248);              // [64]
    float*  sO = (float*)sm;                        // [8][16*68] (phase 2)

    int t = threadIdx.x, w = t >> 5, lane = t & 31;
    int R0 = blockIdx.x * 128;

    for (int i = t; i < 128 * 64; i += 256) {
        int k = i >> 6, j = i & 63;
        sW[k * 72 + j] = __float2half(W[i]);
    }
    #pragma unroll
    for (int q = 0; q < 16; q++) {
        int idx = t + q * 256;
        int row = idx >> 5, c4 = idx & 31;
        float4 v = make_float4(0.f, 0.f, 0.f, 0.f);
        if (R0 + row < n)
            v = *(const float4*)(A + (size_t)(R0 + row) * INF + c4 * 4);
        unsigned u0 = h2_to_u(__floats2half2_rn(v.x, v.y));
        unsigned u1 = h2_to_u(__floats2half2_rn(v.z, v.w));
        *(uint2*)(sA + row * 136 + c4 * 4) = make_uint2(u0, u1);
    }
    if (t < HH) sB[t] = bias[t];
    __syncthreads();

    int row0 = R0 + w * 16;
    bool act = row0 < n;

    wmma::fragment<wmma::accumulator, 16, 16, 16, float> acc[4];
    if (act) {
        #pragma unroll
        for (int nt = 0; nt < 4; nt++) wmma::fill_fragment(acc[nt], 0.0f);
        #pragma unroll
        for (int k = 0; k < 8; k++) {
            wmma::fragment<wmma::matrix_a, 16, 16, 16, __half, wmma::row_major> a;
            wmma::load_matrix_sync(a, sA + (w * 16) * 136 + k * 16, 136);
            #pragma unroll
            for (int nt = 0; nt < 4; nt++) {
                wmma::fragment<wmma::matrix_b, 16, 16, 16, __half, wmma::row_major> b;
                wmma::load_matrix_sync(b, sW + (k * 16) * 72 + nt * 16, 72);
                wmma::mma_sync(acc[nt], a, b, acc[nt]);
            }
        }
    }
    __syncthreads();

    if (act) {
        float* sOw = sO + w * (16 * 68);
        #pragma unroll
        for (int nt = 0; nt < 4; nt++)
            wmma::store_matrix_sync(sOw + nt * 16, acc[nt], 68, wmma::mem_row_major);
        __syncwarp();
        int r = lane >> 1, ch = (lane & 1) * 32;
        int row = row0 + r;
        float dv = g_dinv[row];
        const float* p = sOw + r * 68 + ch;
        float* o = out + (size_t)row * HH + ch;
        __half* oh = outh + (size_t)row * HH + ch;
        #pragma unroll
        for (int j = 0; j < 4; j++) {
            float f0 = p[8*j + 0] + sB[ch + 8*j + 0];
            float f1 = p[8*j + 1] + sB[ch + 8*j + 1];
            float f2 = p[8*j + 2] + sB[ch + 8*j + 2];
            float f3 = p[8*j + 3] + sB[ch + 8*j + 3];
            float f4 = p[8*j + 4] + sB[ch + 8*j + 4];
            float f5 = p[8*j + 5] + sB[ch + 8*j + 5];
            float f6 = p[8*j + 6] + sB[ch + 8*j + 6];
            float f7 = p[8*j + 7] + sB[ch + 8*j + 7];
            *(float4*)(o + 8*j)     = make_float4(f0, f1, f2, f3);
            *(float4*)(o + 8*j + 4) = make_float4(f4, f5, f6, f7);
            uint4 hv;
            hv.x = h2_to_u(__floats2half2_rn(f0 * dv, f1 * dv));
            hv.y = h2_to_u(__floats2half2_rn(f2 * dv, f3 * dv));
            hv.z = h2_to_u(__floats2half2_rn(f4 * dv, f5 * dv));
            hv.w = h2_to_u(__floats2half2_rn(f6 * dv, f7 * dv));
            *(uint4*)(oh + 8*j) = hv;
        }
    }
}

// ------------- fused prop: Agg(t) @ W + cb (+ residual/LN/relu -> t_next) -------------
// Gather: half-warp pairs, LDG.64 per lane, PREDICATED 16-edge batches (tail included)
// so every row is ceil(deg/16) latency round-trips, never serial remainder iterations.
template<bool LAST>
__global__ void __launch_bounds__(512) k_prop(const __half* __restrict__ t,
                                              const float* __restrict__ W,
                                              const float* __restrict__ cb,
                                              const float* __restrict__ ori,
                                              const float* __restrict__ lw,
                                              const float* __restrict__ lb,
                                              void* __restrict__ outp, int n) {
    __shared__ __half sW[64 * 72];     // 9216B
    __shared__ __half sA[16 * 72];     // 2304B
    __shared__ float  sY[16 * 68];     // 4352B

    int tid = threadIdx.x, w = tid >> 5, lane = tid & 31;
    int half = lane >> 4, li = lane & 15;
    int R0 = blockIdx.x * 16;
    int row = R0 + w;

    // stage W fp32->fp16
    #pragma unroll
    for (int q = 0; q < 8; q++) {
        int i = tid + q * 512;
        int k = i >> 6, j = i & 63;
        sW[k * 72 + j] = __float2half(W[i]);
    }

    // phase 1: gather (4 cols per lane: li*4 .. li*4+3)
    float c0 = 0.f, c1 = 0.f, c2 = 0.f, c3 = 0.f;
    float dv = 0.f;
    if (row < n) {
        const u64* x8 = (const u64*)t;   // 16 u64 per row
        // self loop
        {
            u64 v = __ldg(x8 + (size_t)row * 16 + li);
            if (half == 0) {
                float2 f0 = u_to_f2((unsigned)v), f1 = u_to_f2((unsigned)(v >> 32));
                c0 += f0.x; c1 += f0.y; c2 += f1.x; c3 += f1.y;
            }
        }
        int e   = g_ptr[row];
        int end = g_ptr[row + 1];
        for (; e < end; e += 16) {
            #pragma unroll
            for (int k = 0; k < 8; k++) {
                int idx = e + 2 * k + half;
                bool p = idx < end;
                int s = g_csr[p ? idx : e];          // e always valid inside loop
                u64 v = __ldg(x8 + (size_t)s * 16 + li);
                float2 f0 = u_to_f2((unsigned)v), f1 = u_to_f2((unsigned)(v >> 32));
                if (p) { c0 += f0.x; c1 += f0.y; c2 += f1.x; c3 += f1.y; }
            }
        }
        dv = g_dinv[row];
    }
    // combine halves
    c0 += __shfl_xor_sync(0xffffffffu, c0, 16);
    c1 += __shfl_xor_sync(0xffffffffu, c1, 16);
    c2 += __shfl_xor_sync(0xffffffffu, c2, 16);
    c3 += __shfl_xor_sync(0xffffffffu, c3, 16);
    if (half == 0) {
        unsigned p0 = h2_to_u(__floats2half2_rn(c0 * dv, c1 * dv));
        unsigned p1 = h2_to_u(__floats2half2_rn(c2 * dv, c3 * dv));
        *(uint2*)(sA + w * 72 + li * 4) = make_uint2(p0, p1);
    }
    __syncthreads();

    // phase 2: wmma (warps 0-3, one 16-col n-tile each)
    if (w < 4) {
        wmma::fragment<wmma::accumulator, 16, 16, 16, float> acc;
        wmma::fill_fragment(acc, 0.0f);
        #pragma unroll
        for (int k = 0; k < 4; k++) {
            wmma::fragment<wmma::matrix_a, 16, 16, 16, __half, wmma::row_major> a;
            wmma::load_matrix_sync(a, sA + k * 16, 72);
            wmma::fragment<wmma::matrix_b, 16, 16, 16, __half, wmma::row_major> b;
            wmma::load_matrix_sync(b, sW + (k * 16) * 72 + w * 16, 72);
            wmma::mma_sync(acc, a, b, acc);
        }
        wmma::store_matrix_sync(sY + w * 16, acc, 68, wmma::mem_row_major);
    }
    __syncthreads();

    // phase 3: epilogue (warp-per-row)
    if (row < n) {
        float h0 = sY[w * 68 + 2 * lane]     + cb[2 * lane];
        float h1 = sY[w * 68 + 2 * lane + 1] + cb[2 * lane + 1];
        if (LAST) {
            u64 o; PACKAB(o, h0, h1);
            ((u64*)outp)[(size_t)row * 32 + lane] = o;
        } else {
            u64 ov = __ldg((const u64*)ori + (size_t)row * 32 + lane);
            float o0, o1; UNPACK2(o0, o1, ov);
            float x0 = h0 + o0, x1 = h1 + o1;
            float s = x0 + x1;
            #pragma unroll
            for (int off = 16; off; off >>= 1) s += __shfl_xor_sync(0xffffffffu, s, off);
            float mu = s * (1.0f / 64.0f);
            float d0 = x0 - mu, d1 = x1 - mu;
            float q = d0 * d0 + d1 * d1;
            #pragma unroll
            for (int off = 16; off; off >>= 1) q += __shfl_xor_sync(0xffffffffu, q, off);
            float r = rsqrtf(q * (1.0f / 64.0f) + 1e-5f);
            float y0 = fmaxf(fmaf(d0 * r, lw[2 * lane],     lb[2 * lane]),     0.f);
            float y1 = fmaxf(fmaf(d1 * r, lw[2 * lane + 1], lb[2 * lane + 1]), 0.f);
            ((unsigned*)outp)[(size_t)row * 32 + lane] =
                h2_to_u(__floats2half2_rn(y0 * dv, y1 * dv));
        }
    }
}

// ---------------- launcher (serial; lin at profiled slot 3) ----------------
extern "C" void kernel_launch(void* const* d_in, const int* in_sizes, int n_in,
                              void* d_out, int out_size) {
    const float* in_feat = (const float*)d_in[0];
    const int*   ei      = (const int*)  d_in[1];
    const float* lin_w   = (const float*)d_in[2];
    const float* lin_b   = (const float*)d_in[3];
    const float* conv_w  = (const float*)d_in[4];
    const float* conv_b  = (const float*)d_in[5];
    const float* ln_w    = (const float*)d_in[6];
    const float* ln_b    = (const float*)d_in[7];
    float* out = (float*)d_out;

    int n = in_sizes[0] / INF;
    int e = in_sizes[1] / 2;
    const int* src = ei;
    const int* dst = ei + e;
    int e4 = e / 4;
    int nb = (n + 1023) / 1024;

    float  *p_ori;
    __half *p_t0, *p_t1;
    cudaGetSymbolAddress((void**)&p_ori, g_ori);
    cudaGetSymbolAddress((void**)&p_t0,  g_t0);
    cudaGetSymbolAddress((void**)&p_t1,  g_t1);

    cudaFuncSetAttribute(k_lin, cudaFuncAttributeMaxDynamicSharedMemorySize, LN_SMEM);

    int gmm = (n + 127) / 128;
    int gpr = (n + 15) / 16;

    k_count<<<(e4 + 255) / 256, 256>>>((const int4*)dst, e4);                        // 0
    k_scanA<<<nb, 1024>>>(n);                                                        // 1 (+dinv)
    k_scanC<<<nb, 1024>>>(nb, n);                                                    // 2
    k_lin  <<<gmm, 256, LN_SMEM>>>(in_feat, lin_w, lin_b, p_ori, p_t0, n);           // 3 <- profiled
    k_fill <<<(e4 + 255) / 256, 256>>>((const int4*)src, (const int4*)dst, e4);      // 4

    // prop 0: t0 -> t1 (LN params row 1)
    k_prop<false><<<gpr, 512>>>(p_t0, conv_w, conv_b, p_ori, ln_w + 1 * HH, ln_b + 1 * HH, p_t1, n);
    // prop 1: t1 -> t0 (LN params row 2)
    k_prop<false><<<gpr, 512>>>(p_t1, conv_w, conv_b, p_ori, ln_w + 2 * HH, ln_b + 2 * HH, p_t0, n);
    // prop 2: t0 -> out (fp32)
    k_prop<true><<<gpr, 512>>>(p_t0, conv_w, conv_b, nullptr, nullptr, nullptr, out, n);
}

// round 17
// speedup vs baseline: 1.0767x; 1.0767x over previous
#include <cuda_runtime.h>
#include <cuda_fp16.h>
#include <mma.h>

#define NN  100000
#define EE  1600000
#define INF 128
#define HH  64
typedef unsigned long long u64;
using namespace nvcuda;

#define PACKAB(d,a,b) asm("mov.b64 %0,{%1,%2};" : "=l"(d) : "r"(__float_as_uint(a)), "r"(__float_as_uint(b)))
#define UNPACK2(a,b,d) do { unsigned _ua,_ub; \
    asm("mov.b64 {%0,%1},%2;" : "=r"(_ua),"=r"(_ub) : "l"(d)); \
    a=__uint_as_float(_ua); b=__uint_as_float(_ub); } while(0)

__device__ __forceinline__ unsigned h2_to_u(__half2 h) {
    union { __half2 h; unsigned u; } c; c.h = h; return c.u;
}
__device__ __forceinline__ float2 u_to_f2(unsigned u) {
    union { unsigned u; __half2 h; } c; c.u = u; return __half22float2(c.h);
}

// ---------------- device scratch ----------------
__device__ float  g_ori[NN * HH];   // lin output fp32 (residual source)
__device__ __half g_t0 [NN * HH];   // current t (dinv-prescaled, fp16)
__device__ __half g_t1 [NN * HH];   // next t
__device__ float  g_dinv[NN];
__device__ int    g_cnt[NN];        // zero at load; k_fill drains it back to 0
__device__ int    g_ptr[NN + 1];
__device__ int    g_blk[128];
__device__ int    g_csr[EE];

// ---------------- CSR construction ----------------
__global__ void k_count(const int4* __restrict__ dst4, int e4) {
    int i = blockIdx.x * blockDim.x + threadIdx.x;
    if (i < e4) {
        int4 d = dst4[i];
        atomicAdd(&g_cnt[d.x], 1);
        atomicAdd(&g_cnt[d.y], 1);
        atomicAdd(&g_cnt[d.z], 1);
        atomicAdd(&g_cnt[d.w], 1);
    }
}

__global__ void k_scanA(int n) {
    __shared__ int s[1024];
    int tid = threadIdx.x;
    int i = blockIdx.x * 1024 + tid;
    int c = (i < n) ? g_cnt[i] : 0;
    s[tid] = c;
    __syncthreads();
    #pragma unroll
    for (int off = 1; off < 1024; off <<= 1) {
        int t = (tid >= off) ? s[tid - off] : 0;
        __syncthreads();
        s[tid] += t;
        __syncthreads();
    }
    if (i < n) {
        g_ptr[i] = s[tid] - c;
        g_dinv[i] = rsqrtf((float)(c + 1));
    }
    if (tid == 1023) g_blk[blockIdx.x] = s[1023];
}

__global__ void k_scanC(int nb, int n) {
    __shared__ int pref[128];
    int t = threadIdx.x;
    if (t < 128) pref[t] = (t < nb) ? g_blk[t] : 0;
    __syncthreads();
    #pragma unroll
    for (int off = 1; off < 128; off <<= 1) {
        int v = 0;
        if (t < 128 && t >= off) v = pref[t - off];
        __syncthreads();
        if (t < 128) pref[t] += v;
        __syncthreads();
    }
    int b = blockIdx.x;
    int base = (b == 0) ? 0 : pref[b - 1];
    int i = b * 1024 + t;
    if (i < n) g_ptr[i] += base;
    if (b == 0 && t == 0) g_ptr[n] = pref[127];
}

__global__ void k_fill(const int4* __restrict__ src4, const int4* __restrict__ dst4, int e4) {
    int i = blockIdx.x * blockDim.x + threadIdx.x;
    if (i < e4) {
        int4 s = src4[i];
        int4 d = dst4[i];
        g_csr[g_ptr[d.x] + atomicSub(&g_cnt[d.x], 1) - 1] = s.x;
        g_csr[g_ptr[d.y] + atomicSub(&g_cnt[d.y], 1) - 1] = s.y;
        g_csr[g_ptr[d.z] + atomicSub(&g_cnt[d.z], 1) - 1] = s.z;
        g_csr[g_ptr[d.w] + atomicSub(&g_cnt[d.w], 1) - 1] = s.w;
    }
}

// ------------- lin GEMM via wmma: ori = in[n,128] @ W[128,64] + b ; t0 = fp16(dinv*ori) -------------
#define LN_SMEM (18432 + 34816 + 256)
__global__ void __launch_bounds__(256) k_lin(const float* __restrict__ A,
                                             const float* __restrict__ W,
                                             const float* __restrict__ bias,
                                             float* __restrict__ out,
                                             __half* __restrict__ outh, int n) {
    extern __shared__ char sm[];
    __half* sW = (__half*)sm;                       // [128][72]
    __half* sA = (__half*)(sm + 18432);             // [128][136]
    float*  sB = (float*)(sm + 53248);              // [64]
    float*  sO = (float*)sm;                        // [8][16*68] (phase 2)

    int t = threadIdx.x, w = t >> 5, lane = t & 31;
    int R0 = blockIdx.x * 128;

    for (int i = t; i < 128 * 64; i += 256) {
        int k = i >> 6, j = i & 63;
        sW[k * 72 + j] = __float2half(W[i]);
    }
    #pragma unroll
    for (int q = 0; q < 16; q++) {
        int idx = t + q * 256;
        int row = idx >> 5, c4 = idx & 31;
        float4 v = make_float4(0.f, 0.f, 0.f, 0.f);
        if (R0 + row < n)
            v = *(const float4*)(A + (size_t)(R0 + row) * INF + c4 * 4);
        unsigned u0 = h2_to_u(__floats2half2_rn(v.x, v.y));
        unsigned u1 = h2_to_u(__floats2half2_rn(v.z, v.w));
        *(uint2*)(sA + row * 136 + c4 * 4) = make_uint2(u0, u1);
    }
    if (t < HH) sB[t] = bias[t];
    __syncthreads();

    int row0 = R0 + w * 16;
    bool act = row0 < n;

    wmma::fragment<wmma::accumulator, 16, 16, 16, float> acc[4];
    if (act) {
        #pragma unroll
        for (int nt = 0; nt < 4; nt++) wmma::fill_fragment(acc[nt], 0.0f);
        #pragma unroll
        for (int k = 0; k < 8; k++) {
            wmma::fragment<wmma::matrix_a, 16, 16, 16, __half, wmma::row_major> a;
            wmma::load_matrix_sync(a, sA + (w * 16) * 136 + k * 16, 136);
            #pragma unroll
            for (int nt = 0; nt < 4; nt++) {
                wmma::fragment<wmma::matrix_b, 16, 16, 16, __half, wmma::row_major> b;
                wmma::load_matrix_sync(b, sW + (k * 16) * 72 + nt * 16, 72);
                wmma::mma_sync(acc[nt], a, b, acc[nt]);
            }
        }
    }
    __syncthreads();

    if (act) {
        float* sOw = sO + w * (16 * 68);
        #pragma unroll
        for (int nt = 0; nt < 4; nt++)
            wmma::store_matrix_sync(sOw + nt * 16, acc[nt], 68, wmma::mem_row_major);
        __syncwarp();
        int r = lane >> 1, ch = (lane & 1) * 32;
        int row = row0 + r;
        float dv = g_dinv[row];
        const float* p = sOw + r * 68 + ch;
        float* o = out + (size_t)row * HH + ch;
        __half* oh = outh + (size_t)row * HH + ch;
        #pragma unroll
        for (int j = 0; j < 4; j++) {
            float f0 = p[8*j + 0] + sB[ch + 8*j + 0];
            float f1 = p[8*j + 1] + sB[ch + 8*j + 1];
            float f2 = p[8*j + 2] + sB[ch + 8*j + 2];
            float f3 = p[8*j + 3] + sB[ch + 8*j + 3];
            float f4 = p[8*j + 4] + sB[ch + 8*j + 4];
            float f5 = p[8*j + 5] + sB[ch + 8*j + 5];
            float f6 = p[8*j + 6] + sB[ch + 8*j + 6];
            float f7 = p[8*j + 7] + sB[ch + 8*j + 7];
            *(float4*)(o + 8*j)     = make_float4(f0, f1, f2, f3);
            *(float4*)(o + 8*j + 4) = make_float4(f4, f5, f6, f7);
            uint4 hv;
            hv.x = h2_to_u(__floats2half2_rn(f0 * dv, f1 * dv));
            hv.y = h2_to_u(__floats2half2_rn(f2 * dv, f3 * dv));
            hv.z = h2_to_u(__floats2half2_rn(f4 * dv, f5 * dv));
            hv.w = h2_to_u(__floats2half2_rn(f6 * dv, f7 * dv));
            *(uint4*)(oh + 8*j) = hv;
        }
    }
}

// ------------- fused prop: Agg(t) @ W + cb (+ residual/LN/relu -> t_next) -------------
// Gather: half-warp pairs, LDG.64 per lane. Full 16-edge batches (unpredicated),
// then ONE predicated-load tail window (@P LDG issues no transaction when off).
template<bool LAST>
__global__ void __launch_bounds__(512) k_prop(const __half* __restrict__ t,
                                              const float* __restrict__ W,
                                              const float* __restrict__ cb,
                                              const float* __restrict__ ori,
                                              const float* __restrict__ lw,
                                              const float* __restrict__ lb,
                                              void* __restrict__ outp, int n) {
    __shared__ __half sW[64 * 72];     // 9216B
    __shared__ __half sA[16 * 72];     // 2304B
    __shared__ float  sY[16 * 68];     // 4352B

    int tid = threadIdx.x, w = tid >> 5, lane = tid & 31;
    int half = lane >> 4, li = lane & 15;
    int R0 = blockIdx.x * 16;
    int row = R0 + w;

    // stage W fp32->fp16
    #pragma unroll
    for (int q = 0; q < 8; q++) {
        int i = tid + q * 512;
        int k = i >> 6, j = i & 63;
        sW[k * 72 + j] = __float2half(W[i]);
    }

    // phase 1: gather (4 cols per lane: li*4 .. li*4+3)
    float c0 = 0.f, c1 = 0.f, c2 = 0.f, c3 = 0.f;
    float dv = 0.f;
    if (row < n) {
        const u64* x8 = (const u64*)t;   // 16 u64 per row
        // self loop
        {
            u64 v = __ldg(x8 + (size_t)row * 16 + li);
            if (half == 0) {
                float2 f0 = u_to_f2((unsigned)v), f1 = u_to_f2((unsigned)(v >> 32));
                c0 += f0.x; c1 += f0.y; c2 += f1.x; c3 += f1.y;
            }
        }
        int e   = g_ptr[row];
        int end = g_ptr[row + 1];
        // full 16-edge batches
        for (; e + 16 <= end; e += 16) {
            int i0 = g_csr[e +  0 + half];
            int i1 = g_csr[e +  2 + half];
            int i2 = g_csr[e +  4 + half];
            int i3 = g_csr[e +  6 + half];
            int i4 = g_csr[e +  8 + half];
            int i5 = g_csr[e + 10 + half];
            int i6 = g_csr[e + 12 + half];
            int i7 = g_csr[e + 14 + half];
            u64 v0 = __ldg(x8 + (size_t)i0 * 16 + li);
            u64 v1 = __ldg(x8 + (size_t)i1 * 16 + li);
            u64 v2 = __ldg(x8 + (size_t)i2 * 16 + li);
            u64 v3 = __ldg(x8 + (size_t)i3 * 16 + li);
            u64 v4 = __ldg(x8 + (size_t)i4 * 16 + li);
            u64 v5 = __ldg(x8 + (size_t)i5 * 16 + li);
            u64 v6 = __ldg(x8 + (size_t)i6 * 16 + li);
            u64 v7 = __ldg(x8 + (size_t)i7 * 16 + li);
            #define ACC4(v) do { u64 _v = (v); \
                float2 _f0 = u_to_f2((unsigned)_v); \
                float2 _f1 = u_to_f2((unsigned)(_v >> 32)); \
                c0 += _f0.x; c1 += _f0.y; c2 += _f1.x; c3 += _f1.y; } while(0)
            ACC4(v0); ACC4(v1); ACC4(v2); ACC4(v3);
            ACC4(v4); ACC4(v5); ACC4(v6); ACC4(v7);
            #undef ACC4
        }
        // predicated tail window (single batch, @P loads issue nothing when off)
        if (e < end) {
            #pragma unroll
            for (int k = 0; k < 8; k++) {
                int idx = e + 2 * k + half;
                if (idx < end) {
                    int s = g_csr[idx];
                    u64 v = __ldg(x8 + (size_t)s * 16 + li);
                    float2 f0 = u_to_f2((unsigned)v), f1 = u_to_f2((unsigned)(v >> 32));
                    c0 += f0.x; c1 += f0.y; c2 += f1.x; c3 += f1.y;
                }
            }
        }
        dv = g_dinv[row];
    }
    // combine halves
    c0 += __shfl_xor_sync(0xffffffffu, c0, 16);
    c1 += __shfl_xor_sync(0xffffffffu, c1, 16);
    c2 += __shfl_xor_sync(0xffffffffu, c2, 16);
    c3 += __shfl_xor_sync(0xffffffffu, c3, 16);
    if (half == 0) {
        unsigned p0 = h2_to_u(__floats2half2_rn(c0 * dv, c1 * dv));
        unsigned p1 = h2_to_u(__floats2half2_rn(c2 * dv, c3 * dv));
        *(uint2*)(sA + w * 72 + li * 4) = make_uint2(p0, p1);
    }
    __syncthreads();

    // phase 2: wmma (warps 0-3, one 16-col n-tile each)
    if (w < 4) {
        wmma::fragment<wmma::accumulator, 16, 16, 16, float> acc;
        wmma::fill_fragment(acc, 0.0f);
        #pragma unroll
        for (int k = 0; k < 4; k++) {
            wmma::fragment<wmma::matrix_a, 16, 16, 16, __half, wmma::row_major> a;
            wmma::load_matrix_sync(a, sA + k * 16, 72);
            wmma::fragment<wmma::matrix_b, 16, 16, 16, __half, wmma::row_major> b;
            wmma::load_matrix_sync(b, sW + (k * 16) * 72 + w * 16, 72);
            wmma::mma_sync(acc, a, b, acc);
        }
        wmma::store_matrix_sync(sY + w * 16, acc, 68, wmma::mem_row_major);
    }
    __syncthreads();

    // phase 3: epilogue (warp-per-row)
    if (row < n) {
        float h0 = sY[w * 68 + 2 * lane]     + cb[2 * lane];
        float h1 = sY[w * 68 + 2 * lane + 1] + cb[2 * lane + 1];
        if (LAST) {
            u64 o; PACKAB(o, h0, h1);
            ((u64*)outp)[(size_t)row * 32 + lane] = o;
        } else {
            u64 ov = __ldg((const u64*)ori + (size_t)row * 32 + lane);
            float o0, o1; UNPACK2(o0, o1, ov);
            float x0 = h0 + o0, x1 = h1 + o1;
            float s = x0 + x1;
            #pragma unroll
            for (int off = 16; off; off >>= 1) s += __shfl_xor_sync(0xffffffffu, s, off);
            float mu = s * (1.0f / 64.0f);
            float d0 = x0 - mu, d1 = x1 - mu;
            float q = d0 * d0 + d1 * d1;
            #pragma unroll
            for (int off = 16; off; off >>= 1) q += __shfl_xor_sync(0xffffffffu, q, off);
            float r = rsqrtf(q * (1.0f / 64.0f) + 1e-5f);
            float y0 = fmaxf(fmaf(d0 * r, lw[2 * lane],     lb[2 * lane]),     0.f);
            float y1 = fmaxf(fmaf(d1 * r, lw[2 * lane + 1], lb[2 * lane + 1]), 0.f);
            ((unsigned*)outp)[(size_t)row * 32 + lane] =
                h2_to_u(__floats2half2_rn(y0 * dv, y1 * dv));
        }
    }
}

// ---------------- launcher (serial; lin at profiled slot 3) ----------------
extern "C" void kernel_launch(void* const* d_in, const int* in_sizes, int n_in,
                              void* d_out, int out_size) {
    const float* in_feat = (const float*)d_in[0];
    const int*   ei      = (const int*)  d_in[1];
    const float* lin_w   = (const float*)d_in[2];
    const float* lin_b   = (const float*)d_in[3];
    const float* conv_w  = (const float*)d_in[4];
    const float* conv_b  = (const float*)d_in[5];
    const float* ln_w    = (const float*)d_in[6];
    const float* ln_b    = (const float*)d_in[7];
    float* out = (float*)d_out;

    int n = in_sizes[0] / INF;
    int e = in_sizes[1] / 2;
    const int* src = ei;
    const int* dst = ei + e;
    int e4 = e / 4;
    int nb = (n + 1023) / 1024;

    float  *p_ori;
    __half *p_t0, *p_t1;
    cudaGetSymbolAddress((void**)&p_ori, g_ori);
    cudaGetSymbolAddress((void**)&p_t0,  g_t0);
    cudaGetSymbolAddress((void**)&p_t1,  g_t1);

    cudaFuncSetAttribute(k_lin, cudaFuncAttributeMaxDynamicSharedMemorySize, LN_SMEM);

    int gmm = (n + 127) / 128;
    int gpr = (n + 15) / 16;

    k_count<<<(e4 + 255) / 256, 256>>>((const int4*)dst, e4);                        // 0
    k_scanA<<<nb, 1024>>>(n);                                                        // 1 (+dinv)
    k_scanC<<<nb, 1024>>>(nb, n);                                                    // 2
    k_lin  <<<gmm, 256, LN_SMEM>>>(in_feat, lin_w, lin_b, p_ori, p_t0, n);           // 3 <- profiled
    k_fill <<<(e4 + 255) / 256, 256>>>((const int4*)src, (const int4*)dst, e4);      // 4

    // prop 0: t0 -> t1 (LN params row 1)
    k_prop<false><<<gpr, 512>>>(p_t0, conv_w, conv_b, p_ori, ln_w + 1 * HH, ln_b + 1 * HH, p_t1, n);
    // prop 1: t1 -> t0 (LN params row 2)
    k_prop<false><<<gpr, 512>>>(p_t1, conv_w, conv_b, p_ori, ln_w + 2 * HH, ln_b + 2 * HH, p_t0, n);
    // prop 2: t0 -> out (fp32)
    k_prop<true><<<gpr, 512>>>(p_t0, conv_w, conv_b, nullptr, nullptr, nullptr, out, n);
}